// round 17
// baseline (speedup 1.0000x reference)
#include <cuda_runtime.h>
#include <cstdint>

// Problem constants
#define Bsz 16
#define Jn  16
#define Cn  64
#define HW  65536              // 256*256
#define HW4 16384              // float4s per channel
#define NCH (Bsz * Jn)         // 256 channels
#define SEG 4                  // quarter-channel CTAs for dynamic balance
#define NCTA (NCH * SEG)       // 1024 CTAs
#define TPB 512
#define NW  (TPB / 32)         // 16 warps
#define SEGF4 (HW4 / SEG)      // 4096 float4s per segment
#define BATCH 8                // per-thread float4s (= SEGF4/TPB), one batch

// Device-global scratch (allocation-free; zero-initialized at load)
__device__ unsigned long long g_pack[NCH];  // (ordf(v)<<32) | (~float4_idx)
__device__ int                g_cnt[NCH];   // segments done per channel
__device__ float              g_joint[NCH]; // per-(b,j) SSE over C
__device__ int                g_done;       // channels completed

__device__ __forceinline__ unsigned ordf(float f) {
    unsigned u = __float_as_uint(f);
    return (u & 0x80000000u) ? ~u : (u | 0x80000000u);
}
__device__ __forceinline__ float inv_ordf(unsigned p) {
    unsigned u = (p & 0x80000000u) ? (p ^ 0x80000000u) : ~p;
    return __uint_as_float(u);
}

// (value, float4-index) combine: larger value wins, lower index on ties.
__device__ __forceinline__ void argmax_combine(float& v, int& i, float ov, int oi) {
    if (ov > v || (ov == v && oi < i)) { v = ov; i = oi; }
}

// ---------------------------------------------------------------------------
// Quarter-channel CTAs; packed atomicMax combine at float4 granularity; the
// 4th finisher of each channel recovers the element, gathers pred, computes
// the joint SSE; the last channel-completer writes the 16 batch means.
// ---------------------------------------------------------------------------
__global__ __launch_bounds__(TPB, 2)
void fused_label_loss(const float* __restrict__ heatmap,
                      const float* __restrict__ pred,
                      const float* __restrict__ gt,
                      float* __restrict__ out)
{
    const int ch   = blockIdx.x >> 2;          // channel
    const int seg  = blockIdx.x & (SEG - 1);   // quarter within channel
    const int tid  = threadIdx.x;
    const int lane = tid & 31;
    const int warp = tid >> 5;

    const float4* __restrict__ hm =
        reinterpret_cast<const float4*>(heatmap + (size_t)ch * HW);

    const int i0 = seg * SEGF4 + tid;

    // ---- one batch of 8 independent LDG.128 (L2-only), branchless consume --
    float4 v[BATCH];
    #pragma unroll
    for (int k = 0; k < BATCH; ++k)
        v[k] = __ldcg(&hm[i0 + k * TPB]);

    float bv  = -3.402823466e+38f;
    int   bfi = i0;
    #pragma unroll
    for (int k = 0; k < BATCH; ++k) {
        float m01  = fmaxf(v[k].x, v[k].y);
        float m23  = fmaxf(v[k].z, v[k].w);
        float vmax = fmaxf(m01, m23);
        int   fi   = i0 + k * TPB;
        // ascending fi + strict '>' => first occurrence within this thread
        if (vmax > bv) { bv = vmax; bfi = fi; }
    }

    // ---- block argmax reduce on (value, float4 index); 1 barrier ----
    __shared__ float s_v[NW];
    __shared__ int   s_i[NW];
    __shared__ float s_warp[2];
    __shared__ int   s_done, s_idx;

    #pragma unroll
    for (int off = 16; off > 0; off >>= 1) {
        float ov = __shfl_xor_sync(0xFFFFFFFFu, bv, off);
        int   oi = __shfl_xor_sync(0xFFFFFFFFu, bfi, off);
        argmax_combine(bv, bfi, ov, oi);
    }
    if (lane == 0) { s_v[warp] = bv; s_i[warp] = bfi; }
    __syncthreads();

    if (warp == 0) {
        float v0 = (lane < NW) ? s_v[lane] : -3.402823466e+38f;
        int   i1 = (lane < NW) ? s_i[lane] : 0x7FFFFFFF;
        #pragma unroll
        for (int off = 16; off > 0; off >>= 1) {
            float ov = __shfl_xor_sync(0xFFFFFFFFu, v0, off);
            int   oi = __shfl_xor_sync(0xFFFFFFFFu, i1, off);
            argmax_combine(v0, i1, ov, oi);
        }
        if (lane == 0) {
            // publish segment result (float4 granularity preserves global
            // first-occurrence ordering) and detect channel completion
            unsigned long long pk =
                ((unsigned long long)ordf(v0) << 32) |
                (unsigned long long)(0xFFFFFFFFu - (unsigned)i1);
            atomicMax(&g_pack[ch], pk);
            __threadfence();
            int old = atomicAdd(&g_cnt[ch], 1);
            if (old == SEG - 1) {
                __threadfence();
                unsigned long long fin = *(volatile unsigned long long*)&g_pack[ch];
                int   wfi = (int)(0xFFFFFFFFu - (unsigned)(fin & 0xFFFFFFFFull));
                float wv0 = inv_ordf((unsigned)(fin >> 32));
                // recover exact element (descending -> lowest index on tie)
                float4 wv = __ldcg(&hm[wfi]);
                int e = 3;
                if (wv.z == wv0) e = 2;
                if (wv.y == wv0) e = 1;
                if (wv.x == wv0) e = 0;
                s_idx  = wfi * 4 + e;
                s_done = 1;
                g_pack[ch] = 0;   // reset for next graph replay
                g_cnt[ch]  = 0;
            } else {
                s_done = 0;
            }
        }
    }
    __syncthreads();

    if (!s_done) return;

    // ---- channel completer: gather pred @ argmax, squared error over C ----
    const int idx = s_idx;
    const int b   = ch >> 4;
    if (tid < Cn) {
        float p = pred[((size_t)(b * Cn + tid)) * HW + idx];
        float g = gt[(size_t)ch * Cn + tid];     // (b*Jn+j)*Cn == ch*Cn
        float d = p - g;
        float acc = d * d;
        #pragma unroll
        for (int off = 16; off > 0; off >>= 1)
            acc += __shfl_xor_sync(0xFFFFFFFFu, acc, off);
        if (lane == 0) s_warp[warp] = acc;
    }
    __syncthreads();

    // ---- last channel-completer computes the per-batch means ----
    __shared__ int s_last;
    if (tid == 0) {
        g_joint[ch] = s_warp[0] + s_warp[1];
        __threadfence();
        int old = atomicAdd(&g_done, 1);
        s_last = (old == NCH - 1);
        if (s_last) g_done = 0;            // reset for next graph replay
    }
    __syncthreads();

    if (s_last && tid < Bsz) {
        __threadfence();
        float tot = 0.f;
        #pragma unroll
        for (int j = 0; j < Jn; ++j)       // fixed order -> deterministic
            tot += *(volatile float*)&g_joint[tid * Jn + j];
        out[tid] = tot * (1.0f / (float)(Jn * Cn));
    }
}

// ---------------------------------------------------------------------------
extern "C" void kernel_launch(void* const* d_in, const int* in_sizes, int n_in,
                              void* d_out, int out_size)
{
    const float* pred    = (const float*)d_in[0];  // [B,C,H,W]
    const float* gt      = (const float*)d_in[1];  // [B,J,C]
    const float* heatmap = (const float*)d_in[2];  // [B,J,H,W]
    float* out = (float*)d_out;                    // [B]

    fused_label_loss<<<NCTA, TPB>>>(heatmap, pred, gt, out);
}